// round 13
// baseline (speedup 1.0000x reference)
#include <cuda_runtime.h>
#include <math.h>
#include <stdint.h>

// Problem constants
#define BB   2
#define SS   2048
#define EE   1024
#define HH   16
#define DD   64
#define NTOK (BB * SS)   // 4096

// GEMM tiling: CTA 128x256xk32, 8 warps, warp tile 64x64
#define GBM 128
#define GBN 256
#define GBK 32
#define GNIT (EE / GBK)                 // 32
#define NSTG 3
#define A_BYTES (GBM * 128)             // 16384
#define B_BYTES (GBN * 128)             // 32768
#define STG_BYTES (A_BYTES + B_BYTES)   // 49152
#define GEMM_SMEM (NSTG * STG_BYTES)    // 147456

// Attention: CTA q-tile 128, kv-tile 32, 4 warps (32 q-rows each), 3 CTAs/SM
// smem: [stage0: K 8K | V 8K][stage1: K 8K | V 8K][Q 32K] = 64KB
#define AT_STG 16384
#define AT_V   8192
#define AT_Q   32768
#define ATTN_SMEM_BYTES 65536

// ---------------------------------------------------------------------------
// Scratch
// ---------------------------------------------------------------------------
__device__ float g_x[NTOK * EE];             // x, tf32-rounded
__device__ float g_wt[4 * EE * EE];          // Wq^T,Wk^T,Wv^T,Wo^T, rounded
__device__ float g_q[BB * HH * SS * DD];     // [B,H,S,D]
__device__ float g_k[BB * HH * SS * DD];     // [B,H,S,D], tf32-rounded
__device__ float g_v[BB * HH * SS * DD];     // [B,H,D,S] transposed, rounded
__device__ float g_attn[NTOK * EE];          // [B,S,E], tf32-rounded

// ---------------------------------------------------------------------------
// helpers
// ---------------------------------------------------------------------------
__device__ __forceinline__ uint32_t f2tf32(float f)
{
    uint32_t u;
    asm("cvt.rna.tf32.f32 %0, %1;" : "=r"(u) : "f"(f));
    return u;
}

__device__ __forceinline__ uint4 pack_tf32(float4 v)
{
    uint4 u;
    u.x = f2tf32(v.x); u.y = f2tf32(v.y); u.z = f2tf32(v.z); u.w = f2tf32(v.w);
    return u;
}

__device__ __forceinline__ void mma_tf32(float c[4], const uint32_t a[4],
                                         const uint32_t b[2])
{
    asm volatile(
        "mma.sync.aligned.m16n8k8.row.col.f32.tf32.tf32.f32 "
        "{%0,%1,%2,%3}, {%4,%5,%6,%7}, {%8,%9}, {%0,%1,%2,%3};"
        : "+f"(c[0]), "+f"(c[1]), "+f"(c[2]), "+f"(c[3])
        : "r"(a[0]), "r"(a[1]), "r"(a[2]), "r"(a[3]), "r"(b[0]), "r"(b[1]));
}

__device__ __forceinline__ uint32_t s2u(const void* p)
{
    return (uint32_t)__cvta_generic_to_shared(p);
}

__device__ __forceinline__ void cpa16(uint32_t dst, const void* src)
{
    asm volatile("cp.async.cg.shared.global [%0], [%1], 16;"
                 :: "r"(dst), "l"(src) : "memory");
}
__device__ __forceinline__ void cpa_commit()
{
    asm volatile("cp.async.commit_group;" ::: "memory");
}
__device__ __forceinline__ void cpa_wait1()
{
    asm volatile("cp.async.wait_group 1;" ::: "memory");
}
__device__ __forceinline__ void cpa_wait0()
{
    asm volatile("cp.async.wait_group 0;" ::: "memory");
}

__device__ __forceinline__ void ldsm4(uint32_t* r, uint32_t a)
{
    asm volatile("ldmatrix.sync.aligned.m8n8.x4.shared.b16 {%0,%1,%2,%3}, [%4];"
                 : "=r"(r[0]), "=r"(r[1]), "=r"(r[2]), "=r"(r[3]) : "r"(a));
}

__device__ __forceinline__ void sts128(uint32_t a, uint4 v)
{
    asm volatile("st.shared.v4.b32 [%0], {%1,%2,%3,%4};"
                 :: "r"(a), "r"(v.x), "r"(v.y), "r"(v.z), "r"(v.w) : "memory");
}

// 16B-chunk swizzles: 256B rows (16 chunks) and 128B rows (8 chunks)
__device__ __forceinline__ uint32_t swz(int row, int c)
{
    return (uint32_t)(((((c) & 7) ^ ((row) & 7)) | ((c) & 8)) << 4);
}
__device__ __forceinline__ uint32_t swz128(int row, int c)
{
    return (uint32_t)((((c) & 7) ^ ((row) & 7)) << 4);
}

// fast 2^x on the FMA pipe (x <= 0; rel err ~4e-5)
__device__ __forceinline__ float fexp2(float x)
{
    x = fmaxf(x, -100.f);
    float z = x + 12582912.f;
    float f = x - (z - 12582912.f);
    float p = fmaf(f, 0.009618129f, 0.055504109f);
    p = fmaf(f, p, 0.240226507f);
    p = fmaf(f, p, 0.693147181f);
    p = fmaf(f, p, 1.0f);
    int e = (int)((unsigned)__float_as_int(z) << 23);
    return __int_as_float(__float_as_int(p) + e);
}

// ---------------------------------------------------------------------------
// Pre-pass: round x -> g_x
// ---------------------------------------------------------------------------
__global__ void __launch_bounds__(256)
prep_x(const float* __restrict__ x)
{
    const int i = blockIdx.x * 256 + threadIdx.x;
#pragma unroll
    for (int j = 0; j < 4; j++) {
        int idx = i + j * 262144;
        float4 v = ((const float4*)x)[idx];
        uint4 u = pack_tf32(v);
        float4 o;
        o.x = __uint_as_float(u.x); o.y = __uint_as_float(u.y);
        o.z = __uint_as_float(u.z); o.w = __uint_as_float(u.w);
        ((float4*)g_x)[idx] = o;
    }
}

// ---------------------------------------------------------------------------
// Pre-pass: transpose + round W -> g_wt
// ---------------------------------------------------------------------------
__global__ void __launch_bounds__(256)
prep_w(const float* __restrict__ Wq, const float* __restrict__ Wk,
       const float* __restrict__ Wv, const float* __restrict__ Wo)
{
    __shared__ float t[32][33];
    const float* W;
    if (blockIdx.z == 0)      W = Wq;
    else if (blockIdx.z == 1) W = Wk;
    else if (blockIdx.z == 2) W = Wv;
    else                      W = Wo;
    float* out = g_wt + (size_t)blockIdx.z * EE * EE;

    const int n0 = blockIdx.x * 32, k0 = blockIdx.y * 32;
    const int x = threadIdx.x & 31, y = threadIdx.x >> 5;
#pragma unroll
    for (int i = 0; i < 4; i++)
        t[y + 8 * i][x] = W[(size_t)(k0 + y + 8 * i) * EE + n0 + x];
    __syncthreads();
#pragma unroll
    for (int i = 0; i < 4; i++)
        out[(size_t)(n0 + y + 8 * i) * EE + k0 + x] =
            __uint_as_float(f2tf32(t[x][y + 8 * i]));
}

// ---------------------------------------------------------------------------
// GEMM core (unchanged, proven): C[128x256] = A[.,1024] @ Bt^T
// ---------------------------------------------------------------------------
__device__ __forceinline__ void gemm_core(const float* __restrict__ A,
                                          const float* __restrict__ Bt,
                                          int brow, int bcol,
                                          float c[4][8][4], char* sm)
{
    const int tid = threadIdx.x;
    const int w = tid >> 5, l = tid & 31;
    const int wm = w >> 2, wn = w & 3;
    const uint32_t sb = s2u(sm);

    const int r0 = tid >> 3;
    const int kc = tid & 7;
    const float* asrc0 = A + (size_t)(brow + r0) * EE + kc * 4;
    const uint32_t adst0 = (uint32_t)(r0 * 128 + ((kc ^ (r0 & 7)) << 4));
    const float* bsrc0 = Bt + (size_t)(bcol + r0) * EE + kc * 4;
    const uint32_t bdst0 = (uint32_t)(A_BYTES + r0 * 128 + ((kc ^ (r0 & 7)) << 4));

#pragma unroll
    for (int mi = 0; mi < 4; mi++)
#pragma unroll
        for (int ni = 0; ni < 8; ni++)
#pragma unroll
            for (int r = 0; r < 4; r++) c[mi][ni][r] = 0.f;

#pragma unroll
    for (int s = 0; s < 2; s++) {
        uint32_t so = sb + s * STG_BYTES;
        int k0 = s * GBK;
#pragma unroll
        for (int j = 0; j < 4; j++)
            cpa16(so + adst0 + j * 4096, asrc0 + (size_t)j * 32 * EE + k0);
#pragma unroll
        for (int j = 0; j < 8; j++)
            cpa16(so + bdst0 + j * 4096, bsrc0 + (size_t)j * 32 * EE + k0);
        cpa_commit();
    }

    const uint32_t abase = (uint32_t)((wm * 64 + (l & 15)) * 128);
    const int ahalf = l >> 4;
    const int axor = l & 7;
    const uint32_t bbase = (uint32_t)(A_BYTES +
                          (wn * 64 + (l & 7) + ((l >> 4) << 3)) * 128);
    const int bhalf = (l >> 3) & 1;
    const int bxor = l & 7;

    int stage = 0;
    for (int it = 0; it < GNIT; it++) {
        cpa_wait1();
        __syncthreads();

        if (it + 2 < GNIT) {
            int ls = (stage + 2) % NSTG;
            uint32_t so = sb + ls * STG_BYTES;
            int k0 = (it + 2) * GBK;
#pragma unroll
            for (int j = 0; j < 4; j++)
                cpa16(so + adst0 + j * 4096, asrc0 + (size_t)j * 32 * EE + k0);
#pragma unroll
            for (int j = 0; j < 8; j++)
                cpa16(so + bdst0 + j * 4096, bsrc0 + (size_t)j * 32 * EE + k0);
        }
        cpa_commit();

        const uint32_t so = sb + stage * STG_BYTES;

        uint32_t af[2][4][4], bf[2][4][4];
#pragma unroll
        for (int mi = 0; mi < 4; mi++)
            ldsm4(af[0][mi], so + abase + mi * 2048 +
                  ((uint32_t)((ahalf) ^ axor) << 4));
#pragma unroll
        for (int n2 = 0; n2 < 4; n2++)
            ldsm4(bf[0][n2], so + bbase + n2 * 2048 +
                  ((uint32_t)((bhalf) ^ bxor) << 4));

#pragma unroll
        for (int ks = 0; ks < 4; ks++) {
            const int cur = ks & 1;
            if (ks < 3) {
                const int nxt = cur ^ 1;
#pragma unroll
                for (int mi = 0; mi < 4; mi++)
                    ldsm4(af[nxt][mi], so + abase + mi * 2048 +
                          ((uint32_t)((2 * (ks + 1) + ahalf) ^ axor) << 4));
#pragma unroll
                for (int n2 = 0; n2 < 4; n2++)
                    ldsm4(bf[nxt][n2], so + bbase + n2 * 2048 +
                          ((uint32_t)((2 * (ks + 1) + bhalf) ^ bxor) << 4));
            }
#pragma unroll
            for (int mi = 0; mi < 4; mi++)
#pragma unroll
                for (int n2 = 0; n2 < 4; n2++) {
                    mma_tf32(c[mi][2 * n2],     af[cur][mi], &bf[cur][n2][0]);
                    mma_tf32(c[mi][2 * n2 + 1], af[cur][mi], &bf[cur][n2][2]);
                }
        }
        stage = (stage + 1) % NSTG;
    }
}

// ---------------------------------------------------------------------------
// QKV: grid (4, 32, 3). K and V written tf32-pre-rounded.
// ---------------------------------------------------------------------------
__global__ void __launch_bounds__(256, 1)
qkv_mma(const float* __restrict__ bq, const float* __restrict__ bk,
        const float* __restrict__ bv)
{
    extern __shared__ char smc[];
    const float* bias;
    if (blockIdx.z == 0)      bias = bq;
    else if (blockIdx.z == 1) bias = bk;
    else                      bias = bv;
    const float* Bt = g_wt + (size_t)blockIdx.z * EE * EE;

    const int brow = blockIdx.y * GBM;
    const int bcol = blockIdx.x * GBN;

    float c[4][8][4];
    gemm_core(g_x, Bt, brow, bcol, c, smc);

    const int tid = threadIdx.x;
    const int w = tid >> 5, l = tid & 31;
    const int wm = w >> 2, wn = w & 3;

#pragma unroll
    for (int mi = 0; mi < 4; mi++)
#pragma unroll
        for (int ni = 0; ni < 8; ni++) {
            int row0 = brow + wm * 64 + mi * 16 + (l >> 2);
            int col  = bcol + wn * 64 + ni * 8 + (l & 3) * 2;
            float b0 = bias[col], b1 = bias[col + 1];
            int h = col >> 6, d = col & 63;
#pragma unroll
            for (int half = 0; half < 2; half++) {
                int t = row0 + half * 8;
                int b = t >> 11, s = t & 2047;
                float v0 = c[mi][ni][half * 2 + 0] + b0;
                float v1 = c[mi][ni][half * 2 + 1] + b1;
                if (blockIdx.z == 0) {
                    float2 v; v.x = v0; v.y = v1;
                    *(float2*)(g_q + ((size_t)(b * HH + h) * SS + s) * DD + d) = v;
                } else if (blockIdx.z == 1) {
                    float2 v;
                    v.x = __uint_as_float(f2tf32(v0));
                    v.y = __uint_as_float(f2tf32(v1));
                    *(float2*)(g_k + ((size_t)(b * HH + h) * SS + s) * DD + d) = v;
                } else {
                    size_t base = (size_t)(b * HH + h) * DD;
                    g_v[(base + d)     * SS + s] = __uint_as_float(f2tf32(v0));
                    g_v[(base + d + 1) * SS + s] = __uint_as_float(f2tf32(v1));
                }
            }
        }
}

// ---------------------------------------------------------------------------
// Out-proj: grid (4, 32)
// ---------------------------------------------------------------------------
__global__ void __launch_bounds__(256, 1)
proj_mma(const float* __restrict__ bo, float* __restrict__ out)
{
    extern __shared__ char smc[];
    const float* Bt = g_wt + (size_t)3 * EE * EE;

    const int brow = blockIdx.y * GBM;
    const int bcol = blockIdx.x * GBN;

    float c[4][8][4];
    gemm_core(g_attn, Bt, brow, bcol, c, smc);

    const int tid = threadIdx.x;
    const int w = tid >> 5, l = tid & 31;
    const int wm = w >> 2, wn = w & 3;

#pragma unroll
    for (int mi = 0; mi < 4; mi++)
#pragma unroll
        for (int ni = 0; ni < 8; ni++) {
            int row0 = brow + wm * 64 + mi * 16 + (l >> 2);
            int col  = bcol + wn * 64 + ni * 8 + (l & 3) * 2;
            float b0 = bo[col], b1 = bo[col + 1];
#pragma unroll
            for (int half = 0; half < 2; half++) {
                int row = row0 + half * 8;
                float2 v;
                v.x = c[mi][ni][half * 2 + 0] + b0;
                v.y = c[mi][ni][half * 2 + 1] + b1;
                *(float2*)(out + (size_t)row * EE + col) = v;
            }
        }
}

// ---------------------------------------------------------------------------
// Flash attention v3: q-tile 128, kv-tile 32, 4 warps x 32 q-rows, 3 CTAs/SM.
// Q persists in smem (frags reloaded); P relayout via register shuffles.
// grid (16, 32): x -> qt (reversed), y -> bh.
// ---------------------------------------------------------------------------
__global__ void __launch_bounds__(128, 3)
attn_kernel()
{
    extern __shared__ char smc[];
    const uint32_t sb = s2u(smc);

    const int tid = threadIdx.x;
    const int w = tid >> 5, l = tid & 31;
    const int lg = l >> 2, lt = l & 3;
    const int qt = (gridDim.x - 1) - blockIdx.x;
    const int bh = blockIdx.y;
    const int q0 = qt * 128;

    const float* Qg = g_q + (size_t)bh * SS * DD;
    const float* Kg = g_k + (size_t)bh * SS * DD;
    const float* Vg = g_v + (size_t)bh * DD * SS;   // [D,S]

    const int jmax = 4 * qt + 4;

    // cp.async mappings (4 K + 4 V chunks per thread per kv-32 tile)
    // K tile: 32 s-rows x 256B; V tile: 64 d-rows x 128B
    const int kr0 = tid >> 4;                // K row base (stride 8/j2)
    const int kc4 = tid & 15;
    const float* ksrc0 = Kg + (size_t)kr0 * DD + kc4 * 4;
    const uint32_t kdst0 = (uint32_t)(kr0 * 256 + swz(kr0, kc4));
    const int vr0 = tid >> 3;                // V row base (stride 16/j2)
    const int vc4 = tid & 7;
    const float* vsrc0 = Vg + (size_t)vr0 * SS + vc4 * 4;
    const uint32_t vdst0 = (uint32_t)(AT_V + vr0 * 128 + swz128(vr0, vc4));

    // prologue: fetch kv-tile 0 into stage 0
#pragma unroll
    for (int j2 = 0; j2 < 4; j2++) {
        cpa16(sb + kdst0 + j2 * 2048, ksrc0 + (size_t)j2 * 8 * DD);
        cpa16(sb + vdst0 + j2 * 2048, vsrc0 + (size_t)j2 * 16 * SS);
    }
    cpa_commit();

    // load Q tile (scaled + rounded) into AT_Q (persists whole kernel)
    const float qscale = 0.125f * 1.44269504f;
#pragma unroll
    for (int j = 0; j < 16; j++) {
        int p = tid + 128 * j;
        int r = p >> 4, c4 = p & 15;
        float4 v = *(const float4*)(Qg + (size_t)(q0 + r) * DD + c4 * 4);
        v.x *= qscale; v.y *= qscale; v.z *= qscale; v.w *= qscale;
        sts128(sb + AT_Q + r * 256 + swz(r, c4), pack_tf32(v));
    }
    __syncthreads();

    // fragment lane addressing
    const int arow_l = l & 15;
    const int ach = l >> 4;
    const int brow_base = (l & 7) + ((l >> 4) << 3);
    const int bch = (l >> 3) & 1;
    // P shuffle source lanes
    const int srcA = (l & ~3) | (lt >> 1);
    const int srcB = srcA + 2;
    const bool odd = (lt & 1) != 0;

    float m_i[2][2], l_i[2][2];
#pragma unroll
    for (int g = 0; g < 2; g++)
#pragma unroll
        for (int rh = 0; rh < 2; rh++) { m_i[g][rh] = -1e30f; l_i[g][rh] = 0.f; }

    float oacc[2][8][4];
#pragma unroll
    for (int g = 0; g < 2; g++)
#pragma unroll
        for (int ni = 0; ni < 8; ni++)
#pragma unroll
            for (int r = 0; r < 4; r++) oacc[g][ni][r] = 0.f;

    for (int j = 0; j < jmax; j++) {
        const int k0 = j * 32;
        const uint32_t so = sb + (j & 1) * AT_STG;

        cpa_wait0();
        __syncthreads();

        if (j + 1 < jmax) {
            const uint32_t sn = sb + ((j + 1) & 1) * AT_STG;
            const size_t knK = (size_t)(j + 1) * 32 * DD;
            const int knV = (j + 1) * 32;
#pragma unroll
            for (int j2 = 0; j2 < 4; j2++) {
                cpa16(sn + kdst0 + j2 * 2048, ksrc0 + (size_t)j2 * 8 * DD + knK);
                cpa16(sn + vdst0 + j2 * 2048, vsrc0 + (size_t)j2 * 16 * SS + knV);
            }
        }
        cpa_commit();

        const bool active = (k0 <= q0 + w * 32 + 31);
        if (active) {
#pragma unroll
            for (int g = 0; g < 2; g++) {
                const int qrow = w * 32 + g * 16 + arow_l;

                // ---- S = Q @ K^T (16 rows x 32 kv) ----
                float sc[4][4];
#pragma unroll
                for (int ni = 0; ni < 4; ni++)
#pragma unroll
                    for (int r = 0; r < 4; r++) sc[ni][r] = 0.f;

#pragma unroll
                for (int ks = 0; ks < 8; ks++) {
                    uint32_t qa[4];
                    ldsm4(qa, sb + AT_Q + qrow * 256 + swz(qrow, 2 * ks + ach));
#pragma unroll
                    for (int n2 = 0; n2 < 2; n2++) {
                        uint32_t kf[4];
                        int br = n2 * 16 + brow_base;
                        ldsm4(kf, so + br * 256 + swz(br, 2 * ks + bch));
                        mma_tf32(sc[2 * n2],     qa, &kf[0]);
                        mma_tf32(sc[2 * n2 + 1], qa, &kf[2]);
                    }
                }

                // ---- causal mask (possible only on last 4 tiles) ----
                if (j >= 4 * qt) {
#pragma unroll
                    for (int ni = 0; ni < 4; ni++)
#pragma unroll
                        for (int r = 0; r < 4; r++) {
                            int row = q0 + w * 32 + g * 16 + lg + (r >> 1) * 8;
                            int col = k0 + ni * 8 + lt * 2 + (r & 1);
                            if (col > row) sc[ni][r] = -1e30f;
                        }
                }

                // ---- online softmax (base 2, hybrid exp) ----
#pragma unroll
                for (int rh = 0; rh < 2; rh++) {
                    float m = -1e30f;
#pragma unroll
                    for (int ni = 0; ni < 4; ni++) {
                        m = fmaxf(m, sc[ni][rh * 2]);
                        m = fmaxf(m, sc[ni][rh * 2 + 1]);
                    }
                    m = fmaxf(m, __shfl_xor_sync(0xffffffffu, m, 1));
                    m = fmaxf(m, __shfl_xor_sync(0xffffffffu, m, 2));
                    float mnew = fmaxf(m_i[g][rh], m);
                    float f = exp2f(m_i[g][rh] - mnew);
                    float sum = 0.f;
#pragma unroll
                    for (int ni = 0; ni < 4; ni++) {
                        float x0 = sc[ni][rh * 2]     - mnew;
                        float x1 = sc[ni][rh * 2 + 1] - mnew;
                        float p0, p1;
                        if (ni < 3) { p0 = exp2f(x0); p1 = exp2f(x1); }
                        else        { p0 = fexp2(x0); p1 = fexp2(x1); }
                        sc[ni][rh * 2]     = p0;
                        sc[ni][rh * 2 + 1] = p1;
                        sum += p0 + p1;
                    }
                    sum += __shfl_xor_sync(0xffffffffu, sum, 1);
                    sum += __shfl_xor_sync(0xffffffffu, sum, 2);
                    l_i[g][rh] = l_i[g][rh] * f + sum;
                    m_i[g][rh] = mnew;
#pragma unroll
                    for (int ni = 0; ni < 8; ni++) {
                        oacc[g][ni][rh * 2]     *= f;
                        oacc[g][ni][rh * 2 + 1] *= f;
                    }
                }

                // ---- O += P @ V; P A-frags built via shuffles from sc ----
#pragma unroll
                for (int ks = 0; ks < 4; ks++) {
                    uint32_t r0 = f2tf32(sc[ks][0]);
                    uint32_t r1 = f2tf32(sc[ks][1]);
                    uint32_t r2 = f2tf32(sc[ks][2]);
                    uint32_t r3 = f2tf32(sc[ks][3]);
                    uint32_t pa[4];
                    {
                        uint32_t v0 = __shfl_sync(0xffffffffu, r0, srcA);
                        uint32_t v1 = __shfl_sync(0xffffffffu, r1, srcA);
                        pa[0] = odd ? v1 : v0;
                        uint32_t v2 = __shfl_sync(0xffffffffu, r2, srcA);
                        uint32_t v3 = __shfl_sync(0xffffffffu, r3, srcA);
                        pa[1] = odd ? v3 : v2;
                        uint32_t u0 = __shfl_sync(0xffffffffu, r0, srcB);
                        uint32_t u1 = __shfl_sync(0xffffffffu, r1, srcB);
                        pa[2] = odd ? u1 : u0;
                        uint32_t u2 = __shfl_sync(0xffffffffu, r2, srcB);
                        uint32_t u3 = __shfl_sync(0xffffffffu, r3, srcB);
                        pa[3] = odd ? u3 : u2;
                    }
#pragma unroll
                    for (int n2 = 0; n2 < 4; n2++) {
                        uint32_t vf[4];
                        int vr = n2 * 16 + brow_base;
                        ldsm4(vf, so + AT_V + vr * 128 +
                              swz128(vr, 2 * ks + bch));
                        mma_tf32(oacc[g][2 * n2],     pa, &vf[0]);
                        mma_tf32(oacc[g][2 * n2 + 1], pa, &vf[2]);
                    }
                }
            }
        }
    }

    // ---- epilogue: normalize, round, write [B,S,E] ----
    const int b = bh >> 4;
    const int h = bh & 15;
#pragma unroll
    for (int g = 0; g < 2; g++)
#pragma unroll
        for (int rh = 0; rh < 2; rh++) {
            float inv = 1.f / l_i[g][rh];
#pragma unroll
            for (int ni = 0; ni < 8; ni++) {
                int s = q0 + w * 32 + g * 16 + lg + rh * 8;
                int e = h * 64 + ni * 8 + lt * 2;
                float2 v;
                v.x = __uint_as_float(f2tf32(oacc[g][ni][rh * 2]     * inv));
                v.y = __uint_as_float(f2tf32(oacc[g][ni][rh * 2 + 1] * inv));
                *(float2*)(g_attn + (size_t)(b * SS + s) * EE + e) = v;
            }
        }
}

// ---------------------------------------------------------------------------
// Launch
// ---------------------------------------------------------------------------
extern "C" void kernel_launch(void* const* d_in, const int* in_sizes, int n_in,
                              void* d_out, int out_size)
{
    const float* x  = (const float*)d_in[0];
    const float* Wq = (const float*)d_in[1];
    const float* bq = (const float*)d_in[2];
    const float* Wk = (const float*)d_in[3];
    const float* bk = (const float*)d_in[4];
    const float* Wv = (const float*)d_in[5];
    const float* bv = (const float*)d_in[6];
    const float* Wo = (const float*)d_in[7];
    const float* bo = (const float*)d_in[8];
    float* out = (float*)d_out;

    (void)cudaFuncSetAttribute(qkv_mma,
                               cudaFuncAttributeMaxDynamicSharedMemorySize,
                               GEMM_SMEM);
    (void)cudaFuncSetAttribute(proj_mma,
                               cudaFuncAttributeMaxDynamicSharedMemorySize,
                               GEMM_SMEM);
    (void)cudaFuncSetAttribute(attn_kernel,
                               cudaFuncAttributeMaxDynamicSharedMemorySize,
                               ATTN_SMEM_BYTES);

    prep_x<<<1024, 256>>>(x);
    prep_w<<<dim3(32, 32, 4), 256>>>(Wq, Wk, Wv, Wo);

    dim3 gq(EE / GBN, NTOK / GBM, 3);
    qkv_mma<<<gq, 256, GEMM_SMEM>>>(bq, bk, bv);

    dim3 ga(SS / 128, BB * HH);
    attn_kernel<<<ga, 128, ATTN_SMEM_BYTES>>>();

    dim3 gp(EE / GBN, NTOK / GBM);
    proj_mma<<<gp, 256, GEMM_SMEM>>>(bo, out);
}

// round 14
// speedup vs baseline: 1.0584x; 1.0584x over previous
#include <cuda_runtime.h>
#include <math.h>
#include <stdint.h>

// Problem constants
#define BB   2
#define SS   2048
#define EE   1024
#define HH   16
#define DD   64
#define NTOK (BB * SS)   // 4096

// GEMM tiling: CTA 128x128xk32, 8 warps, warp tile 64x32, 2 CTAs/SM
#define GBM 128
#define GBN 128
#define GBK 32
#define GNIT (EE / GBK)                 // 32
#define NSTG 3
#define A_BYTES (GBM * 128)             // 16384
#define B_BYTES (GBN * 128)             // 16384
#define STG_BYTES (A_BYTES + B_BYTES)   // 32768
#define GEMM_SMEM (NSTG * STG_BYTES)    // 98304

// Attention: CTA q-tile 128, kv-tile 64, 4 warps (32 q-rows each)  [R12 proven]
// smem: [stage0: K 16K | V 16K][stage1: K 16K | V 16K][Q/P 32K] = 96KB
#define AT_STG 32768
#define AT_V   16384
#define AT_P   65536
#define ATTN_SMEM_BYTES 98304

// ---------------------------------------------------------------------------
// Scratch
// ---------------------------------------------------------------------------
__device__ float g_x[NTOK * EE];             // x, tf32-rounded
__device__ float g_wt[4 * EE * EE];          // Wq^T,Wk^T,Wv^T,Wo^T, rounded
__device__ float g_q[BB * HH * SS * DD];     // [B,H,S,D]
__device__ float g_k[BB * HH * SS * DD];     // [B,H,S,D], tf32-rounded
__device__ float g_v[BB * HH * SS * DD];     // [B,H,D,S] transposed, rounded
__device__ float g_attn[NTOK * EE];          // [B,S,E], tf32-rounded

// ---------------------------------------------------------------------------
// helpers
// ---------------------------------------------------------------------------
__device__ __forceinline__ uint32_t f2tf32(float f)
{
    uint32_t u;
    asm("cvt.rna.tf32.f32 %0, %1;" : "=r"(u) : "f"(f));
    return u;
}

__device__ __forceinline__ uint4 pack_tf32(float4 v)
{
    uint4 u;
    u.x = f2tf32(v.x); u.y = f2tf32(v.y); u.z = f2tf32(v.z); u.w = f2tf32(v.w);
    return u;
}

__device__ __forceinline__ void mma_tf32(float c[4], const uint32_t a[4],
                                         const uint32_t b[2])
{
    asm volatile(
        "mma.sync.aligned.m16n8k8.row.col.f32.tf32.tf32.f32 "
        "{%0,%1,%2,%3}, {%4,%5,%6,%7}, {%8,%9}, {%0,%1,%2,%3};"
        : "+f"(c[0]), "+f"(c[1]), "+f"(c[2]), "+f"(c[3])
        : "r"(a[0]), "r"(a[1]), "r"(a[2]), "r"(a[3]), "r"(b[0]), "r"(b[1]));
}

__device__ __forceinline__ uint32_t s2u(const void* p)
{
    return (uint32_t)__cvta_generic_to_shared(p);
}

__device__ __forceinline__ void cpa16(uint32_t dst, const void* src)
{
    asm volatile("cp.async.cg.shared.global [%0], [%1], 16;"
                 :: "r"(dst), "l"(src) : "memory");
}
__device__ __forceinline__ void cpa_commit()
{
    asm volatile("cp.async.commit_group;" ::: "memory");
}
__device__ __forceinline__ void cpa_wait1()
{
    asm volatile("cp.async.wait_group 1;" ::: "memory");
}
__device__ __forceinline__ void cpa_wait0()
{
    asm volatile("cp.async.wait_group 0;" ::: "memory");
}

__device__ __forceinline__ void ldsm4(uint32_t* r, uint32_t a)
{
    asm volatile("ldmatrix.sync.aligned.m8n8.x4.shared.b16 {%0,%1,%2,%3}, [%4];"
                 : "=r"(r[0]), "=r"(r[1]), "=r"(r[2]), "=r"(r[3]) : "r"(a));
}

__device__ __forceinline__ void sts128(uint32_t a, uint4 v)
{
    asm volatile("st.shared.v4.b32 [%0], {%1,%2,%3,%4};"
                 :: "r"(a), "r"(v.x), "r"(v.y), "r"(v.z), "r"(v.w) : "memory");
}

__device__ __forceinline__ void sts64v(uint32_t a, uint32_t x, uint32_t y)
{
    asm volatile("st.shared.v2.b32 [%0], {%1,%2};"
                 :: "r"(a), "r"(x), "r"(y) : "memory");
}

// 16B-chunk swizzle within rows of 256B: chunk' = ((c&7)^(row&7)) | (c&8)
__device__ __forceinline__ uint32_t swz(int row, int c)
{
    return (uint32_t)(((((c) & 7) ^ ((row) & 7)) | ((c) & 8)) << 4);
}

// fast 2^x on the FMA pipe (x <= 0; rel err ~4e-5)
__device__ __forceinline__ float fexp2(float x)
{
    x = fmaxf(x, -100.f);
    float z = x + 12582912.f;
    float f = x - (z - 12582912.f);
    float p = fmaf(f, 0.009618129f, 0.055504109f);
    p = fmaf(f, p, 0.240226507f);
    p = fmaf(f, p, 0.693147181f);
    p = fmaf(f, p, 1.0f);
    int e = (int)((unsigned)__float_as_int(z) << 23);
    return __int_as_float(__float_as_int(p) + e);
}

// ---------------------------------------------------------------------------
// Pre-pass: round x -> g_x
// ---------------------------------------------------------------------------
__global__ void __launch_bounds__(256)
prep_x(const float* __restrict__ x)
{
    const int i = blockIdx.x * 256 + threadIdx.x;
#pragma unroll
    for (int j = 0; j < 4; j++) {
        int idx = i + j * 262144;
        float4 v = ((const float4*)x)[idx];
        uint4 u = pack_tf32(v);
        float4 o;
        o.x = __uint_as_float(u.x); o.y = __uint_as_float(u.y);
        o.z = __uint_as_float(u.z); o.w = __uint_as_float(u.w);
        ((float4*)g_x)[idx] = o;
    }
}

// ---------------------------------------------------------------------------
// Pre-pass: transpose + round W -> g_wt
// ---------------------------------------------------------------------------
__global__ void __launch_bounds__(256)
prep_w(const float* __restrict__ Wq, const float* __restrict__ Wk,
       const float* __restrict__ Wv, const float* __restrict__ Wo)
{
    __shared__ float t[32][33];
    const float* W;
    if (blockIdx.z == 0)      W = Wq;
    else if (blockIdx.z == 1) W = Wk;
    else if (blockIdx.z == 2) W = Wv;
    else                      W = Wo;
    float* out = g_wt + (size_t)blockIdx.z * EE * EE;

    const int n0 = blockIdx.x * 32, k0 = blockIdx.y * 32;
    const int x = threadIdx.x & 31, y = threadIdx.x >> 5;
#pragma unroll
    for (int i = 0; i < 4; i++)
        t[y + 8 * i][x] = W[(size_t)(k0 + y + 8 * i) * EE + n0 + x];
    __syncthreads();
#pragma unroll
    for (int i = 0; i < 4; i++)
        out[(size_t)(n0 + y + 8 * i) * EE + k0 + x] =
            __uint_as_float(f2tf32(t[x][y + 8 * i]));
}

// ---------------------------------------------------------------------------
// GEMM core: C[128x128] = A[.,1024] @ Bt^T. 8 warps, warp tile 64x32.
// 3-stage cp.async pipeline; single-buffered ldmatrix fragments (16 warps/SM
// hide the LDS latency). ~110 regs -> 2 CTAs/SM.
// ---------------------------------------------------------------------------
__device__ __forceinline__ void gemm_core(const float* __restrict__ A,
                                          const float* __restrict__ Bt,
                                          int brow, int bcol,
                                          float c[4][4][4], char* sm)
{
    const int tid = threadIdx.x;
    const int w = tid >> 5, l = tid & 31;
    const int wm = w >> 2, wn = w & 3;
    const uint32_t sb = s2u(sm);

    // Linear cp.async mappings (row stride 32 per j; row&7 invariant)
    const int r0 = tid >> 3;
    const int kc = tid & 7;
    const float* asrc0 = A + (size_t)(brow + r0) * EE + kc * 4;
    const uint32_t adst0 = (uint32_t)(r0 * 128 + ((kc ^ (r0 & 7)) << 4));
    const float* bsrc0 = Bt + (size_t)(bcol + r0) * EE + kc * 4;
    const uint32_t bdst0 = (uint32_t)(A_BYTES + r0 * 128 + ((kc ^ (r0 & 7)) << 4));

#pragma unroll
    for (int mi = 0; mi < 4; mi++)
#pragma unroll
        for (int ni = 0; ni < 4; ni++)
#pragma unroll
            for (int r = 0; r < 4; r++) c[mi][ni][r] = 0.f;

#pragma unroll
    for (int s = 0; s < 2; s++) {
        uint32_t so = sb + s * STG_BYTES;
        int k0 = s * GBK;
#pragma unroll
        for (int j = 0; j < 4; j++) {
            cpa16(so + adst0 + j * 4096, asrc0 + (size_t)j * 32 * EE + k0);
            cpa16(so + bdst0 + j * 4096, bsrc0 + (size_t)j * 32 * EE + k0);
        }
        cpa_commit();
    }

    const uint32_t abase = (uint32_t)((wm * 64 + (l & 15)) * 128);
    const int ahalf = l >> 4;
    const int axor = l & 7;
    const uint32_t bbase = (uint32_t)(A_BYTES +
                          (wn * 32 + (l & 7) + ((l >> 4) << 3)) * 128);
    const int bhalf = (l >> 3) & 1;
    const int bxor = l & 7;

    int stage = 0;
    for (int it = 0; it < GNIT; it++) {
        cpa_wait1();
        __syncthreads();

        if (it + 2 < GNIT) {
            int ls = (stage + 2) % NSTG;
            uint32_t so = sb + ls * STG_BYTES;
            int k0 = (it + 2) * GBK;
#pragma unroll
            for (int j = 0; j < 4; j++) {
                cpa16(so + adst0 + j * 4096, asrc0 + (size_t)j * 32 * EE + k0);
                cpa16(so + bdst0 + j * 4096, bsrc0 + (size_t)j * 32 * EE + k0);
            }
        }
        cpa_commit();

        const uint32_t so = sb + stage * STG_BYTES;
#pragma unroll
        for (int ks = 0; ks < 4; ks++) {
            uint32_t af[4][4], bf[2][4];
#pragma unroll
            for (int mi = 0; mi < 4; mi++)
                ldsm4(af[mi], so + abase + mi * 2048 +
                      ((uint32_t)((2 * ks + ahalf) ^ axor) << 4));
#pragma unroll
            for (int n2 = 0; n2 < 2; n2++)
                ldsm4(bf[n2], so + bbase + n2 * 2048 +
                      ((uint32_t)((2 * ks + bhalf) ^ bxor) << 4));
#pragma unroll
            for (int mi = 0; mi < 4; mi++)
#pragma unroll
                for (int n2 = 0; n2 < 2; n2++) {
                    mma_tf32(c[mi][2 * n2],     af[mi], &bf[n2][0]);
                    mma_tf32(c[mi][2 * n2 + 1], af[mi], &bf[n2][2]);
                }
        }
        stage = (stage + 1) % NSTG;
    }
}

// ---------------------------------------------------------------------------
// QKV: grid (8, 32, 3). K and V written tf32-pre-rounded.
// ---------------------------------------------------------------------------
__global__ void __launch_bounds__(256, 2)
qkv_mma(const float* __restrict__ bq, const float* __restrict__ bk,
        const float* __restrict__ bv)
{
    extern __shared__ char smc[];
    const float* bias;
    if (blockIdx.z == 0)      bias = bq;
    else if (blockIdx.z == 1) bias = bk;
    else                      bias = bv;
    const float* Bt = g_wt + (size_t)blockIdx.z * EE * EE;

    const int brow = blockIdx.y * GBM;
    const int bcol = blockIdx.x * GBN;

    float c[4][4][4];
    gemm_core(g_x, Bt, brow, bcol, c, smc);

    const int tid = threadIdx.x;
    const int w = tid >> 5, l = tid & 31;
    const int wm = w >> 2, wn = w & 3;

#pragma unroll
    for (int mi = 0; mi < 4; mi++)
#pragma unroll
        for (int ni = 0; ni < 4; ni++) {
            int row0 = brow + wm * 64 + mi * 16 + (l >> 2);
            int col  = bcol + wn * 32 + ni * 8 + (l & 3) * 2;
            float b0 = bias[col], b1 = bias[col + 1];
            int h = col >> 6, d = col & 63;
#pragma unroll
            for (int half = 0; half < 2; half++) {
                int t = row0 + half * 8;
                int b = t >> 11, s = t & 2047;
                float v0 = c[mi][ni][half * 2 + 0] + b0;
                float v1 = c[mi][ni][half * 2 + 1] + b1;
                if (blockIdx.z == 0) {
                    float2 v; v.x = v0; v.y = v1;
                    *(float2*)(g_q + ((size_t)(b * HH + h) * SS + s) * DD + d) = v;
                } else if (blockIdx.z == 1) {
                    float2 v;
                    v.x = __uint_as_float(f2tf32(v0));
                    v.y = __uint_as_float(f2tf32(v1));
                    *(float2*)(g_k + ((size_t)(b * HH + h) * SS + s) * DD + d) = v;
                } else {
                    size_t base = (size_t)(b * HH + h) * DD;
                    g_v[(base + d)     * SS + s] = __uint_as_float(f2tf32(v0));
                    g_v[(base + d + 1) * SS + s] = __uint_as_float(f2tf32(v1));
                }
            }
        }
}

// ---------------------------------------------------------------------------
// Out-proj: grid (8, 32)
// ---------------------------------------------------------------------------
__global__ void __launch_bounds__(256, 2)
proj_mma(const float* __restrict__ bo, float* __restrict__ out)
{
    extern __shared__ char smc[];
    const float* Bt = g_wt + (size_t)3 * EE * EE;

    const int brow = blockIdx.y * GBM;
    const int bcol = blockIdx.x * GBN;

    float c[4][4][4];
    gemm_core(g_attn, Bt, brow, bcol, c, smc);

    const int tid = threadIdx.x;
    const int w = tid >> 5, l = tid & 31;
    const int wm = w >> 2, wn = w & 3;

#pragma unroll
    for (int mi = 0; mi < 4; mi++)
#pragma unroll
        for (int ni = 0; ni < 4; ni++) {
            int row0 = brow + wm * 64 + mi * 16 + (l >> 2);
            int col  = bcol + wn * 32 + ni * 8 + (l & 3) * 2;
            float b0 = bo[col], b1 = bo[col + 1];
#pragma unroll
            for (int half = 0; half < 2; half++) {
                int row = row0 + half * 8;
                float2 v;
                v.x = c[mi][ni][half * 2 + 0] + b0;
                v.y = c[mi][ni][half * 2 + 1] + b1;
                *(float2*)(out + (size_t)row * EE + col) = v;
            }
        }
}

// ---------------------------------------------------------------------------
// Flash attention (R12 proven config): q-tile 128, kv-tile 64, 4 warps x 32
// q-rows, cp.async double-buffered K/V, qa hoisted, P via smem.
// grid (16, 32): x -> qt (reversed), y -> bh.
// ---------------------------------------------------------------------------
__global__ void __launch_bounds__(128, 2)
attn_kernel()
{
    extern __shared__ char smc[];
    const uint32_t sb = s2u(smc);

    const int tid = threadIdx.x;
    const int w = tid >> 5, l = tid & 31;
    const int lg = l >> 2, lt = l & 3;
    const int qt = (gridDim.x - 1) - blockIdx.x;
    const int bh = blockIdx.y;
    const int q0 = qt * 128;

    const float* Qg = g_q + (size_t)bh * SS * DD;
    const float* Kg = g_k + (size_t)bh * SS * DD;
    const float* Vg = g_v + (size_t)bh * DD * SS;   // [D,S]

    const int jmax = 2 * qt + 2;

    // Linear cp.async mappings: row stride 8 per j2 (row&7 invariant)
    const int kr0 = tid >> 4;
    const int kc4 = tid & 15;
    const float* ksrc0 = Kg + (size_t)kr0 * DD + kc4 * 4;
    const float* vsrc0 = Vg + (size_t)kr0 * SS + kc4 * 4;
    const uint32_t kdst0 = (uint32_t)(kr0 * 256 + swz(kr0, kc4));
    const uint32_t vdst0 = (uint32_t)(AT_V + kr0 * 256 + swz(kr0, kc4));

    // prologue: fetch kv-tile 0 into stage 0
#pragma unroll
    for (int j2 = 0; j2 < 8; j2++) {
        cpa16(sb + kdst0 + j2 * 2048, ksrc0 + (size_t)j2 * 8 * DD);
        cpa16(sb + vdst0 + j2 * 2048, vsrc0 + (size_t)j2 * 8 * SS);
    }
    cpa_commit();

    // load Q tile (scaled + rounded) into P region, hoist fragments
    const float qscale = 0.125f * 1.44269504f;
#pragma unroll
    for (int j = 0; j < 16; j++) {
        int p = tid + 128 * j;
        int r = p >> 4, c4 = p & 15;
        float4 v = *(const float4*)(Qg + (size_t)(q0 + r) * DD + c4 * 4);
        v.x *= qscale; v.y *= qscale; v.z *= qscale; v.w *= qscale;
        sts128(sb + AT_P + r * 256 + swz(r, c4), pack_tf32(v));
    }
    __syncthreads();

    const int arow_l = l & 15;
    const int ach = l >> 4;
    uint32_t qa[2][8][4];
#pragma unroll
    for (int g = 0; g < 2; g++) {
        int row = w * 32 + g * 16 + arow_l;
#pragma unroll
        for (int ks = 0; ks < 8; ks++)
            ldsm4(qa[g][ks], sb + AT_P + row * 256 + swz(row, 2 * ks + ach));
    }

    const int brow_base = (l & 7) + ((l >> 4) << 3);
    const int bch = (l >> 3) & 1;

    float m_i[2][2], l_i[2][2];
#pragma unroll
    for (int g = 0; g < 2; g++)
#pragma unroll
        for (int rh = 0; rh < 2; rh++) { m_i[g][rh] = -1e30f; l_i[g][rh] = 0.f; }

    float oacc[2][8][4];
#pragma unroll
    for (int g = 0; g < 2; g++)
#pragma unroll
        for (int ni = 0; ni < 8; ni++)
#pragma unroll
            for (int r = 0; r < 4; r++) oacc[g][ni][r] = 0.f;

    for (int j = 0; j < jmax; j++) {
        const int k0 = j * 64;
        const uint32_t so = sb + (j & 1) * AT_STG;

        cpa_wait0();
        __syncthreads();

        if (j + 1 < jmax) {
            const uint32_t sn = sb + ((j + 1) & 1) * AT_STG;
            const size_t knK = (size_t)(j + 1) * 64 * DD;
            const int knV = (j + 1) * 64;
#pragma unroll
            for (int j2 = 0; j2 < 8; j2++) {
                cpa16(sn + kdst0 + j2 * 2048, ksrc0 + (size_t)j2 * 8 * DD + knK);
                cpa16(sn + vdst0 + j2 * 2048, vsrc0 + (size_t)j2 * 8 * SS + knV);
            }
        }
        cpa_commit();

        const bool active = (k0 <= q0 + w * 32 + 31);
        if (active) {
#pragma unroll
            for (int g = 0; g < 2; g++) {
                float sc[8][4];
#pragma unroll
                for (int ni = 0; ni < 8; ni++)
#pragma unroll
                    for (int r = 0; r < 4; r++) sc[ni][r] = 0.f;

#pragma unroll
                for (int ks = 0; ks < 8; ks++) {
#pragma unroll
                    for (int n2 = 0; n2 < 4; n2++) {
                        uint32_t kf[4];
                        int br = n2 * 16 + brow_base;
                        ldsm4(kf, so + br * 256 + swz(br, 2 * ks + bch));
                        mma_tf32(sc[2 * n2],     qa[g][ks], &kf[0]);
                        mma_tf32(sc[2 * n2 + 1], qa[g][ks], &kf[2]);
                    }
                }

                if (j >= 2 * qt) {
#pragma unroll
                    for (int ni = 0; ni < 8; ni++)
#pragma unroll
                        for (int r = 0; r < 4; r++) {
                            int row = q0 + w * 32 + g * 16 + lg + (r >> 1) * 8;
                            int col = k0 + ni * 8 + lt * 2 + (r & 1);
                            if (col > row) sc[ni][r] = -1e30f;
                        }
                }

#pragma unroll
                for (int rh = 0; rh < 2; rh++) {
                    float m = -1e30f;
#pragma unroll
                    for (int ni = 0; ni < 8; ni++) {
                        m = fmaxf(m, sc[ni][rh * 2]);
                        m = fmaxf(m, sc[ni][rh * 2 + 1]);
                    }
                    m = fmaxf(m, __shfl_xor_sync(0xffffffffu, m, 1));
                    m = fmaxf(m, __shfl_xor_sync(0xffffffffu, m, 2));
                    float mnew = fmaxf(m_i[g][rh], m);
                    float f = exp2f(m_i[g][rh] - mnew);
                    float sum = 0.f;
#pragma unroll
                    for (int ni = 0; ni < 8; ni++) {
                        float x0 = sc[ni][rh * 2]     - mnew;
                        float x1 = sc[ni][rh * 2 + 1] - mnew;
                        float p0, p1;
                        if (ni < 6) { p0 = exp2f(x0); p1 = exp2f(x1); }
                        else        { p0 = fexp2(x0); p1 = fexp2(x1); }
                        sc[ni][rh * 2]     = p0;
                        sc[ni][rh * 2 + 1] = p1;
                        sum += p0 + p1;
                    }
                    sum += __shfl_xor_sync(0xffffffffu, sum, 1);
                    sum += __shfl_xor_sync(0xffffffffu, sum, 2);
                    l_i[g][rh] = l_i[g][rh] * f + sum;
                    m_i[g][rh] = mnew;
#pragma unroll
                    for (int ni = 0; ni < 8; ni++) {
                        oacc[g][ni][rh * 2]     *= f;
                        oacc[g][ni][rh * 2 + 1] *= f;
                    }
                }

#pragma unroll
                for (int ni = 0; ni < 8; ni++)
#pragma unroll
                    for (int rh = 0; rh < 2; rh++) {
                        int row = w * 32 + g * 16 + lg + rh * 8;
                        int c = ni * 2 + (lt >> 1);
                        sts64v(sb + AT_P + row * 256 + swz(row, c) + (lt & 1) * 8,
                               f2tf32(sc[ni][rh * 2]), f2tf32(sc[ni][rh * 2 + 1]));
                    }
            }
            __syncwarp();

#pragma unroll
            for (int ks = 0; ks < 8; ks++) {
                uint32_t pa[2][4];
#pragma unroll
                for (int g = 0; g < 2; g++) {
                    int row = w * 32 + g * 16 + arow_l;
                    ldsm4(pa[g], sb + AT_P + row * 256 + swz(row, 2 * ks + ach));
                }
#pragma unroll
                for (int n2 = 0; n2 < 4; n2++) {
                    uint32_t vf[4];
                    int vr = n2 * 16 + brow_base;
                    ldsm4(vf, so + AT_V + vr * 256 + swz(vr, 2 * ks + bch));
#pragma unroll
                    for (int g = 0; g < 2; g++) {
                        mma_tf32(oacc[g][2 * n2],     pa[g], &vf[0]);
                        mma_tf32(oacc[g][2 * n2 + 1], pa[g], &vf[2]);
                    }
                }
            }
            __syncwarp();
        }
    }

    // epilogue: normalize, round, write [B,S,E]
    const int b = bh >> 4;
    const int h = bh & 15;
#pragma unroll
    for (int g = 0; g < 2; g++)
#pragma unroll
        for (int rh = 0; rh < 2; rh++) {
            float inv = 1.f / l_i[g][rh];
#pragma unroll
            for (int ni = 0; ni < 8; ni++) {
                int s = q0 + w * 32 + g * 16 + lg + rh * 8;
                int e = h * 64 + ni * 8 + lt * 2;
                float2 v;
                v.x = __uint_as_float(f2tf32(oacc[g][ni][rh * 2]     * inv));
                v.y = __uint_as_float(f2tf32(oacc[g][ni][rh * 2 + 1] * inv));
                *(float2*)(g_attn + (size_t)(b * SS + s) * EE + e) = v;
            }
        }
}

// ---------------------------------------------------------------------------
// Launch
// ---------------------------------------------------------------------------
extern "C" void kernel_launch(void* const* d_in, const int* in_sizes, int n_in,
                              void* d_out, int out_size)
{
    const float* x  = (const float*)d_in[0];
    const float* Wq = (const float*)d_in[1];
    const float* bq = (const float*)d_in[2];
    const float* Wk = (const float*)d_in[3];
    const float* bk = (const float*)d_in[4];
    const float* Wv = (const float*)d_in[5];
    const float* bv = (const float*)d_in[6];
    const float* Wo = (const float*)d_in[7];
    const float* bo = (const float*)d_in[8];
    float* out = (float*)d_out;

    (void)cudaFuncSetAttribute(qkv_mma,
                               cudaFuncAttributeMaxDynamicSharedMemorySize,
                               GEMM_SMEM);
    (void)cudaFuncSetAttribute(proj_mma,
                               cudaFuncAttributeMaxDynamicSharedMemorySize,
                               GEMM_SMEM);
    (void)cudaFuncSetAttribute(attn_kernel,
                               cudaFuncAttributeMaxDynamicSharedMemorySize,
                               ATTN_SMEM_BYTES);

    prep_x<<<1024, 256>>>(x);
    prep_w<<<dim3(32, 32, 4), 256>>>(Wq, Wk, Wv, Wo);

    dim3 gq(EE / GBN, NTOK / GBM, 3);
    qkv_mma<<<gq, 256, GEMM_SMEM>>>(bq, bk, bv);

    dim3 ga(SS / 128, BB * HH);
    attn_kernel<<<ga, 128, ATTN_SMEM_BYTES>>>();

    dim3 gp(EE / GBN, NTOK / GBM);
    proj_mma<<<gp, 256, GEMM_SMEM>>>(bo, out);
}